// round 7
// baseline (speedup 1.0000x reference)
#include <cuda_runtime.h>
#include <cuda_bf16.h>
#include <math.h>

// ---------------------------------------------------------------------------
// LLaDA router: logits = x @ W^T  (N tokens, D feat, E=8 experts)
//   -> LayerNorm(E) -> /(|T|+1e-6) -> softmax -> top-2 dispatch
//   -> router_loss = 0.01*mean(rl^2) + 0.01*KL(ideal||actual)/E
// Out layout: [routing_weights N*E][dispatch N*E][loss 1]
//
// 2 tokens/warp, expert-pair f32x2 accumulators, distance-2 register
// prefetch on x, persistent-ish grid (444 blocks x tile loop), fused
// per-tile partials + last-tile loss reduction.
// ---------------------------------------------------------------------------

#define EXPERTS 8
#define TOK_PER_WARP 2
#define WARPS_PER_BLOCK 8
#define TOK_PER_BLOCK (TOK_PER_WARP * WARPS_PER_BLOCK)   // 16
#define MAX_TILES 8192
#define GRID_BLOCKS 444                                   // 3 per SM * 148

__device__ float g_part[MAX_TILES * 9];
__device__ unsigned int g_ctr = 0;

typedef unsigned long long u64;

__device__ __forceinline__ u64 pk2(float lo, float hi) {
    u64 r;
    asm("mov.b64 %0, {%1, %2};" : "=l"(r) : "f"(lo), "f"(hi));
    return r;
}
__device__ __forceinline__ u64 fma2(u64 a, u64 b, u64 c) {
    u64 d;
    asm("fma.rn.f32x2 %0, %1, %2, %3;" : "=l"(d) : "l"(a), "l"(b), "l"(c));
    return d;
}
__device__ __forceinline__ u64 add2(u64 a, u64 b) {
    u64 d;
    asm("add.rn.f32x2 %0, %1, %2;" : "=l"(d) : "l"(a), "l"(b));
    return d;
}
__device__ __forceinline__ void unpk2(u64 v, float& lo, float& hi) {
    asm("mov.b64 {%0, %1}, %2;" : "=f"(lo), "=f"(hi) : "l"(v));
}
__device__ __forceinline__ float f4c(const float4& v, int d) {
    return (d == 0) ? v.x : (d == 1) ? v.y : (d == 2) ? v.z : v.w;
}

template <int DD>   // DD = compile-time D (2048 fast path), 0 = runtime D
__global__ __launch_bounds__(256, 3)
void router_main(const float* __restrict__ x,
                 const float* __restrict__ W,
                 const float* __restrict__ gamma,
                 const float* __restrict__ beta,
                 const float* __restrict__ temp,
                 float* __restrict__ out,
                 int N, int Drt, int nTiles)
{
    const int D = DD ? DD : Drt;
    const int Dq = D >> 2;                       // D in float4 units
    const int nIter = D >> 7;                    // 128 floats per warp sweep

    __shared__ float s_logits[TOK_PER_BLOCK * EXPERTS];
    __shared__ bool s_last;

    const int lane = threadIdx.x & 31;
    const int warp = threadIdx.x >> 5;
    const float4* wq = (const float4*)W + lane;

    for (int tile = blockIdx.x; tile < nTiles; tile += GRID_BLOCKS) {
        const int tok0 = tile * TOK_PER_BLOCK + warp * TOK_PER_WARP;
        const int t0 = min(tok0 + 0, N - 1);     // clamp tail (dup, masked)
        const int t1 = min(tok0 + 1, N - 1);
        const float4* xq0 = (const float4*)x + (size_t)t0 * Dq + lane;
        const float4* xq1 = (const float4*)x + (size_t)t1 * Dq + lane;

        u64 acc[TOK_PER_WARP][EXPERTS / 2];
#pragma unroll
        for (int t = 0; t < TOK_PER_WARP; ++t)
#pragma unroll
            for (int j = 0; j < EXPERTS / 2; ++j) acc[t][j] = 0ull;

        // distance-2 software pipeline on x
        float4 c0 = __ldg(xq0);
        float4 c1 = __ldg(xq1);
        const int i1c = min(1, nIter - 1);
        float4 n0 = __ldg(xq0 + (size_t)i1c * 32);
        float4 n1 = __ldg(xq1 + (size_t)i1c * 32);

        for (int i = 0; i < nIter; ++i) {
            const int ip = min(i + 2, nIter - 1);     // branchless prefetch idx
            float4 f0 = __ldg(xq0 + (size_t)ip * 32);
            float4 f1 = __ldg(xq1 + (size_t)ip * 32);

            u64 xx0[4], xx1[4];
#pragma unroll
            for (int d = 0; d < 4; ++d) {
                xx0[d] = pk2(f4c(c0, d), f4c(c0, d));
                xx1[d] = pk2(f4c(c1, d), f4c(c1, d));
            }

#pragma unroll
            for (int h = 0; h < 2; ++h) {             // experts [4h, 4h+4)
                float4 wv[4];
#pragma unroll
                for (int e = 0; e < 4; ++e)
                    wv[e] = __ldg(wq + (size_t)(h * 4 + e) * Dq + (size_t)i * 32);
#pragma unroll
                for (int d = 0; d < 4; ++d) {
                    u64 wp0 = pk2(f4c(wv[0], d), f4c(wv[1], d));
                    u64 wp1 = pk2(f4c(wv[2], d), f4c(wv[3], d));
                    acc[0][h * 2 + 0] = fma2(xx0[d], wp0, acc[0][h * 2 + 0]);
                    acc[0][h * 2 + 1] = fma2(xx0[d], wp1, acc[0][h * 2 + 1]);
                    acc[1][h * 2 + 0] = fma2(xx1[d], wp0, acc[1][h * 2 + 0]);
                    acc[1][h * 2 + 1] = fma2(xx1[d], wp1, acc[1][h * 2 + 1]);
                }
            }
            c0 = n0; c1 = n1; n0 = f0; n1 = f1;
        }

        // butterfly reduce 8 packed accumulators across the warp
#pragma unroll
        for (int m = 16; m >= 1; m >>= 1)
#pragma unroll
            for (int t = 0; t < TOK_PER_WARP; ++t)
#pragma unroll
                for (int j = 0; j < EXPERTS / 2; ++j)
                    acc[t][j] = add2(acc[t][j],
                                     __shfl_xor_sync(0xFFFFFFFFu, acc[t][j], m));

        if (lane == 0) {
#pragma unroll
            for (int t = 0; t < TOK_PER_WARP; ++t)
#pragma unroll
                for (int j = 0; j < EXPERTS / 2; ++j) {
                    float lo, hi;
                    unpk2(acc[t][j], lo, hi);
                    const int lt = warp * TOK_PER_WARP + t;
                    s_logits[lt * EXPERTS + 2 * j + 0] = lo;
                    s_logits[lt * EXPERTS + 2 * j + 1] = hi;
                }
        }
        __syncthreads();

        // ---- epilogue: lanes 0..15 handle this tile's 16 tokens -----------
        if (threadIdx.x < TOK_PER_BLOCK) {
            const int lt = threadIdx.x;
            const int g = tile * TOK_PER_BLOCK + lt;
            const bool valid = (g < N);

            const float tinv = 1.0f / (fabsf(temp[0]) + 1e-6f);
            float gm[EXPERTS], bt[EXPERTS];
#pragma unroll
            for (int e = 0; e < EXPERTS; ++e) { gm[e] = gamma[e]; bt[e] = beta[e]; }

            float l[EXPERTS];
            float mu = 0.0f;
#pragma unroll
            for (int e = 0; e < EXPERTS; ++e) {
                l[e] = s_logits[lt * EXPERTS + e];
                mu += l[e];
            }
            mu *= (1.0f / EXPERTS);
            float var = 0.0f;
#pragma unroll
            for (int e = 0; e < EXPERTS; ++e) {
                float dlt = l[e] - mu;
                var += dlt * dlt;
            }
            var *= (1.0f / EXPERTS);
            const float rinv = rsqrtf(var + 1e-5f);

            float rl[EXPERTS];
            float zsum = 0.0f;
            float mx = -1e30f;
#pragma unroll
            for (int e = 0; e < EXPERTS; ++e) {
                float v = ((l[e] - mu) * rinv * gm[e] + bt[e]) * tinv;
                rl[e] = v;
                zsum += v * v;
                mx = fmaxf(mx, v);
            }
            float rw[EXPERTS];
            float ssum = 0.0f;
#pragma unroll
            for (int e = 0; e < EXPERTS; ++e) {
                rw[e] = expf(rl[e] - mx);
                ssum += rw[e];
            }
            const float sinv = 1.0f / ssum;
#pragma unroll
            for (int e = 0; e < EXPERTS; ++e) rw[e] *= sinv;

            // top-2 (lowest index wins ties, matching lax.top_k)
            int i1 = 0; float w1 = rw[0];
#pragma unroll
            for (int e = 1; e < EXPERTS; ++e)
                if (rw[e] > w1) { w1 = rw[e]; i1 = e; }
            int i2 = -1; float w2 = -1.0f;
#pragma unroll
            for (int e = 0; e < EXPERTS; ++e)
                if (e != i1 && rw[e] > w2) { w2 = rw[e]; i2 = e; }
            const float nrm = 1.0f / (w1 + w2 + 1e-6f);
            const float d1 = w1 * nrm, d2 = w2 * nrm;

            if (valid) {
                const size_t NE = (size_t)N * EXPERTS;
                float4* rwo = (float4*)(out + (size_t)g * EXPERTS);
                rwo[0] = make_float4(rw[0], rw[1], rw[2], rw[3]);
                rwo[1] = make_float4(rw[4], rw[5], rw[6], rw[7]);
                float disp[EXPERTS];
#pragma unroll
                for (int e = 0; e < EXPERTS; ++e)
                    disp[e] = (e == i1) ? d1 : (e == i2) ? d2 : 0.0f;
                float4* dpo = (float4*)(out + NE + (size_t)g * EXPERTS);
                dpo[0] = make_float4(disp[0], disp[1], disp[2], disp[3]);
                dpo[1] = make_float4(disp[4], disp[5], disp[6], disp[7]);
            }

            // 16-lane reduction of tile partials, then single store
            float zc = valid ? zsum : 0.0f;
            float ec[EXPERTS];
#pragma unroll
            for (int e = 0; e < EXPERTS; ++e) ec[e] = valid ? rw[e] : 0.0f;

#pragma unroll
            for (int m = 8; m >= 1; m >>= 1) {
                zc += __shfl_xor_sync(0x0000FFFFu, zc, m);
#pragma unroll
                for (int e = 0; e < EXPERTS; ++e)
                    ec[e] += __shfl_xor_sync(0x0000FFFFu, ec[e], m);
            }
            if (lane == 0) {
                float* p = &g_part[(size_t)tile * 9];
#pragma unroll
                for (int e = 0; e < EXPERTS; ++e) p[e] = ec[e];
                p[8] = zc;
            }
        }
        __syncthreads();

        // ---- per-tile ticket; last tile triggers the loss reduction -------
        if (threadIdx.x == 0) {
            __threadfence();
            unsigned int t = atomicAdd(&g_ctr, 1u);
            s_last = (t == (unsigned int)(nTiles - 1));
        }
        __syncthreads();

        if (s_last) {
            __shared__ float s_red[9];
            for (int c = warp; c < 9; c += WARPS_PER_BLOCK) {
                float v = 0.0f;
                for (int k = lane; k < nTiles; k += 32)
                    v += g_part[(size_t)k * 9 + c];
#pragma unroll
                for (int m = 16; m >= 1; m >>= 1)
                    v += __shfl_xor_sync(0xFFFFFFFFu, v, m);
                if (lane == 0) s_red[c] = v;
            }
            __syncthreads();
            if (threadIdx.x == 0) {
                const float invN = 1.0f / (float)N;
                float z = s_red[8] * invN * (1.0f / EXPERTS);
                float lb = 0.0f;
                const float ideal = 1.0f / EXPERTS;
#pragma unroll
                for (int e = 0; e < EXPERTS; ++e) {
                    float actual = s_red[e] * invN;
                    lb += ideal * (logf(ideal) - logf(actual));
                }
                lb *= (1.0f / EXPERTS);
                out[(size_t)2 * N * EXPERTS] = 0.01f * z + 0.01f * lb;
                g_ctr = 0;   // reset for next graph replay (deterministic)
            }
            __syncthreads();
        }
    }
}

extern "C" void kernel_launch(void* const* d_in, const int* in_sizes, int n_in,
                              void* d_out, int out_size)
{
    const float* x     = (const float*)d_in[0];
    const float* W     = (const float*)d_in[1];
    const float* gamma = (const float*)d_in[2];
    const float* beta  = (const float*)d_in[3];
    const float* temp  = (const float*)d_in[4];
    float* out = (float*)d_out;

    const int E = in_sizes[2];           // 8
    const int D = in_sizes[1] / E;       // 2048
    const int N = in_sizes[0] / D;       // 16384

    const int nTiles = (N + TOK_PER_BLOCK - 1) / TOK_PER_BLOCK;
    const int grid = nTiles < GRID_BLOCKS ? nTiles : GRID_BLOCKS;

    if (D == 2048)
        router_main<2048><<<grid, 256>>>(x, W, gamma, beta, temp, out, N, D, nTiles);
    else
        router_main<0><<<grid, 256>>>(x, W, gamma, beta, temp, out, N, D, nTiles);
}

// round 8
// speedup vs baseline: 1.0093x; 1.0093x over previous
#include <cuda_runtime.h>
#include <cuda_bf16.h>
#include <math.h>

// ---------------------------------------------------------------------------
// LLaDA router: logits = x @ W^T  (N tokens, D feat, E=8 experts)
//   -> LayerNorm(E) -> /(|T|+1e-6) -> softmax -> top-2 dispatch
//   -> router_loss = 0.01*mean(rl^2) + 0.01*KL(ideal||actual)/E
// Out layout: [routing_weights N*E][dispatch N*E][loss 1]
//
// 2 tokens/warp, expert-pair f32x2 accumulators, distance-2 register
// prefetch on x, persistent-ish grid (444 blocks x tile loop), fused
// per-tile partials + last-tile loss reduction.
// ---------------------------------------------------------------------------

#define EXPERTS 8
#define TOK_PER_WARP 2
#define WARPS_PER_BLOCK 8
#define TOK_PER_BLOCK (TOK_PER_WARP * WARPS_PER_BLOCK)   // 16
#define MAX_TILES 8192
#define GRID_BLOCKS 444                                   // 3 per SM * 148

__device__ float g_part[MAX_TILES * 9];
__device__ unsigned int g_ctr = 0;

typedef unsigned long long u64;

__device__ __forceinline__ u64 pk2(float lo, float hi) {
    u64 r;
    asm("mov.b64 %0, {%1, %2};" : "=l"(r) : "f"(lo), "f"(hi));
    return r;
}
__device__ __forceinline__ u64 fma2(u64 a, u64 b, u64 c) {
    u64 d;
    asm("fma.rn.f32x2 %0, %1, %2, %3;" : "=l"(d) : "l"(a), "l"(b), "l"(c));
    return d;
}
__device__ __forceinline__ u64 add2(u64 a, u64 b) {
    u64 d;
    asm("add.rn.f32x2 %0, %1, %2;" : "=l"(d) : "l"(a), "l"(b));
    return d;
}
__device__ __forceinline__ void unpk2(u64 v, float& lo, float& hi) {
    asm("mov.b64 {%0, %1}, %2;" : "=f"(lo), "=f"(hi) : "l"(v));
}
__device__ __forceinline__ float f4c(const float4& v, int d) {
    return (d == 0) ? v.x : (d == 1) ? v.y : (d == 2) ? v.z : v.w;
}

template <int DD>   // DD = compile-time D (2048 fast path), 0 = runtime D
__global__ __launch_bounds__(256, 3)
void router_main(const float* __restrict__ x,
                 const float* __restrict__ W,
                 const float* __restrict__ gamma,
                 const float* __restrict__ beta,
                 const float* __restrict__ temp,
                 float* __restrict__ out,
                 int N, int Drt, int nTiles)
{
    const int D = DD ? DD : Drt;
    const int Dq = D >> 2;                       // D in float4 units
    const int nIter = D >> 7;                    // 128 floats per warp sweep

    __shared__ float s_logits[TOK_PER_BLOCK * EXPERTS];
    __shared__ bool s_last;

    const int lane = threadIdx.x & 31;
    const int warp = threadIdx.x >> 5;
    const float4* wq = (const float4*)W + lane;

    for (int tile = blockIdx.x; tile < nTiles; tile += GRID_BLOCKS) {
        const int tok0 = tile * TOK_PER_BLOCK + warp * TOK_PER_WARP;
        const int t0 = min(tok0 + 0, N - 1);     // clamp tail (dup, masked)
        const int t1 = min(tok0 + 1, N - 1);
        const float4* xq0 = (const float4*)x + (size_t)t0 * Dq + lane;
        const float4* xq1 = (const float4*)x + (size_t)t1 * Dq + lane;

        u64 acc[TOK_PER_WARP][EXPERTS / 2];
#pragma unroll
        for (int t = 0; t < TOK_PER_WARP; ++t)
#pragma unroll
            for (int j = 0; j < EXPERTS / 2; ++j) acc[t][j] = 0ull;

        // distance-2 software pipeline on x
        float4 c0 = __ldg(xq0);
        float4 c1 = __ldg(xq1);
        const int i1c = min(1, nIter - 1);
        float4 n0 = __ldg(xq0 + (size_t)i1c * 32);
        float4 n1 = __ldg(xq1 + (size_t)i1c * 32);

        for (int i = 0; i < nIter; ++i) {
            const int ip = min(i + 2, nIter - 1);     // branchless prefetch idx
            float4 f0 = __ldg(xq0 + (size_t)ip * 32);
            float4 f1 = __ldg(xq1 + (size_t)ip * 32);

            u64 xx0[4], xx1[4];
#pragma unroll
            for (int d = 0; d < 4; ++d) {
                xx0[d] = pk2(f4c(c0, d), f4c(c0, d));
                xx1[d] = pk2(f4c(c1, d), f4c(c1, d));
            }

#pragma unroll
            for (int h = 0; h < 2; ++h) {             // experts [4h, 4h+4)
                float4 wv[4];
#pragma unroll
                for (int e = 0; e < 4; ++e)
                    wv[e] = __ldg(wq + (size_t)(h * 4 + e) * Dq + (size_t)i * 32);
#pragma unroll
                for (int d = 0; d < 4; ++d) {
                    u64 wp0 = pk2(f4c(wv[0], d), f4c(wv[1], d));
                    u64 wp1 = pk2(f4c(wv[2], d), f4c(wv[3], d));
                    acc[0][h * 2 + 0] = fma2(xx0[d], wp0, acc[0][h * 2 + 0]);
                    acc[0][h * 2 + 1] = fma2(xx0[d], wp1, acc[0][h * 2 + 1]);
                    acc[1][h * 2 + 0] = fma2(xx1[d], wp0, acc[1][h * 2 + 0]);
                    acc[1][h * 2 + 1] = fma2(xx1[d], wp1, acc[1][h * 2 + 1]);
                }
            }
            c0 = n0; c1 = n1; n0 = f0; n1 = f1;
        }

        // butterfly reduce 8 packed accumulators across the warp
#pragma unroll
        for (int m = 16; m >= 1; m >>= 1)
#pragma unroll
            for (int t = 0; t < TOK_PER_WARP; ++t)
#pragma unroll
                for (int j = 0; j < EXPERTS / 2; ++j)
                    acc[t][j] = add2(acc[t][j],
                                     __shfl_xor_sync(0xFFFFFFFFu, acc[t][j], m));

        if (lane == 0) {
#pragma unroll
            for (int t = 0; t < TOK_PER_WARP; ++t)
#pragma unroll
                for (int j = 0; j < EXPERTS / 2; ++j) {
                    float lo, hi;
                    unpk2(acc[t][j], lo, hi);
                    const int lt = warp * TOK_PER_WARP + t;
                    s_logits[lt * EXPERTS + 2 * j + 0] = lo;
                    s_logits[lt * EXPERTS + 2 * j + 1] = hi;
                }
        }
        __syncthreads();

        // ---- epilogue: lanes 0..15 handle this tile's 16 tokens -----------
        if (threadIdx.x < TOK_PER_BLOCK) {
            const int lt = threadIdx.x;
            const int g = tile * TOK_PER_BLOCK + lt;
            const bool valid = (g < N);

            const float tinv = 1.0f / (fabsf(temp[0]) + 1e-6f);
            float gm[EXPERTS], bt[EXPERTS];
#pragma unroll
            for (int e = 0; e < EXPERTS; ++e) { gm[e] = gamma[e]; bt[e] = beta[e]; }

            float l[EXPERTS];
            float mu = 0.0f;
#pragma unroll
            for (int e = 0; e < EXPERTS; ++e) {
                l[e] = s_logits[lt * EXPERTS + e];
                mu += l[e];
            }
            mu *= (1.0f / EXPERTS);
            float var = 0.0f;
#pragma unroll
            for (int e = 0; e < EXPERTS; ++e) {
                float dlt = l[e] - mu;
                var += dlt * dlt;
            }
            var *= (1.0f / EXPERTS);
            const float rinv = rsqrtf(var + 1e-5f);

            float rl[EXPERTS];
            float zsum = 0.0f;
            float mx = -1e30f;
#pragma unroll
            for (int e = 0; e < EXPERTS; ++e) {
                float v = ((l[e] - mu) * rinv * gm[e] + bt[e]) * tinv;
                rl[e] = v;
                zsum += v * v;
                mx = fmaxf(mx, v);
            }
            float rw[EXPERTS];
            float ssum = 0.0f;
#pragma unroll
            for (int e = 0; e < EXPERTS; ++e) {
                rw[e] = expf(rl[e] - mx);
                ssum += rw[e];
            }
            const float sinv = 1.0f / ssum;
#pragma unroll
            for (int e = 0; e < EXPERTS; ++e) rw[e] *= sinv;

            // top-2 (lowest index wins ties, matching lax.top_k)
            int i1 = 0; float w1 = rw[0];
#pragma unroll
            for (int e = 1; e < EXPERTS; ++e)
                if (rw[e] > w1) { w1 = rw[e]; i1 = e; }
            int i2 = -1; float w2 = -1.0f;
#pragma unroll
            for (int e = 0; e < EXPERTS; ++e)
                if (e != i1 && rw[e] > w2) { w2 = rw[e]; i2 = e; }
            const float nrm = 1.0f / (w1 + w2 + 1e-6f);
            const float d1 = w1 * nrm, d2 = w2 * nrm;

            if (valid) {
                const size_t NE = (size_t)N * EXPERTS;
                float4* rwo = (float4*)(out + (size_t)g * EXPERTS);
                rwo[0] = make_float4(rw[0], rw[1], rw[2], rw[3]);
                rwo[1] = make_float4(rw[4], rw[5], rw[6], rw[7]);
                float disp[EXPERTS];
#pragma unroll
                for (int e = 0; e < EXPERTS; ++e)
                    disp[e] = (e == i1) ? d1 : (e == i2) ? d2 : 0.0f;
                float4* dpo = (float4*)(out + NE + (size_t)g * EXPERTS);
                dpo[0] = make_float4(disp[0], disp[1], disp[2], disp[3]);
                dpo[1] = make_float4(disp[4], disp[5], disp[6], disp[7]);
            }

            // 16-lane reduction of tile partials, then single store
            float zc = valid ? zsum : 0.0f;
            float ec[EXPERTS];
#pragma unroll
            for (int e = 0; e < EXPERTS; ++e) ec[e] = valid ? rw[e] : 0.0f;

#pragma unroll
            for (int m = 8; m >= 1; m >>= 1) {
                zc += __shfl_xor_sync(0x0000FFFFu, zc, m);
#pragma unroll
                for (int e = 0; e < EXPERTS; ++e)
                    ec[e] += __shfl_xor_sync(0x0000FFFFu, ec[e], m);
            }
            if (lane == 0) {
                float* p = &g_part[(size_t)tile * 9];
#pragma unroll
                for (int e = 0; e < EXPERTS; ++e) p[e] = ec[e];
                p[8] = zc;
            }
        }
        __syncthreads();

        // ---- per-tile ticket; last tile triggers the loss reduction -------
        if (threadIdx.x == 0) {
            __threadfence();
            unsigned int t = atomicAdd(&g_ctr, 1u);
            s_last = (t == (unsigned int)(nTiles - 1));
        }
        __syncthreads();

        if (s_last) {
            __shared__ float s_red[9];
            for (int c = warp; c < 9; c += WARPS_PER_BLOCK) {
                float v = 0.0f;
                for (int k = lane; k < nTiles; k += 32)
                    v += g_part[(size_t)k * 9 + c];
#pragma unroll
                for (int m = 16; m >= 1; m >>= 1)
                    v += __shfl_xor_sync(0xFFFFFFFFu, v, m);
                if (lane == 0) s_red[c] = v;
            }
            __syncthreads();
            if (threadIdx.x == 0) {
                const float invN = 1.0f / (float)N;
                float z = s_red[8] * invN * (1.0f / EXPERTS);
                float lb = 0.0f;
                const float ideal = 1.0f / EXPERTS;
#pragma unroll
                for (int e = 0; e < EXPERTS; ++e) {
                    float actual = s_red[e] * invN;
                    lb += ideal * (logf(ideal) - logf(actual));
                }
                lb *= (1.0f / EXPERTS);
                out[(size_t)2 * N * EXPERTS] = 0.01f * z + 0.01f * lb;
                g_ctr = 0;   // reset for next graph replay (deterministic)
            }
            __syncthreads();
        }
    }
}

extern "C" void kernel_launch(void* const* d_in, const int* in_sizes, int n_in,
                              void* d_out, int out_size)
{
    const float* x     = (const float*)d_in[0];
    const float* W     = (const float*)d_in[1];
    const float* gamma = (const float*)d_in[2];
    const float* beta  = (const float*)d_in[3];
    const float* temp  = (const float*)d_in[4];
    float* out = (float*)d_out;

    const int E = in_sizes[2];           // 8
    const int D = in_sizes[1] / E;       // 2048
    const int N = in_sizes[0] / D;       // 16384

    const int nTiles = (N + TOK_PER_BLOCK - 1) / TOK_PER_BLOCK;
    const int grid = nTiles < GRID_BLOCKS ? nTiles : GRID_BLOCKS;

    if (D == 2048)
        router_main<2048><<<grid, 256>>>(x, W, gamma, beta, temp, out, N, D, nTiles);
    else
        router_main<0><<<grid, 256>>>(x, W, gamma, beta, temp, out, N, D, nTiles);
}

// round 9
// speedup vs baseline: 1.0153x; 1.0059x over previous
#include <cuda_runtime.h>
#include <cuda_bf16.h>
#include <math.h>

// ---------------------------------------------------------------------------
// LLaDA router: logits = x @ W^T  (N tokens, D feat, E=8 experts)
//   -> LayerNorm(E) -> /(|T|+1e-6) -> softmax -> top-2 dispatch
//   -> router_loss = 0.01*mean(rl^2) + 0.01*KL(ideal||actual)/E
// Out layout: [routing_weights N*E][dispatch N*E][loss 1]
//
// 2 tokens/warp, expert-pair f32x2 accumulators, distance-2 register
// prefetch on x, persistent-ish grid (444 blocks x tile loop), fused
// per-tile partials + last-tile loss reduction.
// ---------------------------------------------------------------------------

#define EXPERTS 8
#define TOK_PER_WARP 2
#define WARPS_PER_BLOCK 8
#define TOK_PER_BLOCK (TOK_PER_WARP * WARPS_PER_BLOCK)   // 16
#define MAX_TILES 8192
#define GRID_BLOCKS 444                                   // 3 per SM * 148

__device__ float g_part[MAX_TILES * 9];
__device__ unsigned int g_ctr = 0;

typedef unsigned long long u64;

__device__ __forceinline__ u64 pk2(float lo, float hi) {
    u64 r;
    asm("mov.b64 %0, {%1, %2};" : "=l"(r) : "f"(lo), "f"(hi));
    return r;
}
__device__ __forceinline__ u64 fma2(u64 a, u64 b, u64 c) {
    u64 d;
    asm("fma.rn.f32x2 %0, %1, %2, %3;" : "=l"(d) : "l"(a), "l"(b), "l"(c));
    return d;
}
__device__ __forceinline__ u64 add2(u64 a, u64 b) {
    u64 d;
    asm("add.rn.f32x2 %0, %1, %2;" : "=l"(d) : "l"(a), "l"(b));
    return d;
}
__device__ __forceinline__ void unpk2(u64 v, float& lo, float& hi) {
    asm("mov.b64 {%0, %1}, %2;" : "=f"(lo), "=f"(hi) : "l"(v));
}
__device__ __forceinline__ float f4c(const float4& v, int d) {
    return (d == 0) ? v.x : (d == 1) ? v.y : (d == 2) ? v.z : v.w;
}

template <int DD>   // DD = compile-time D (2048 fast path), 0 = runtime D
__global__ __launch_bounds__(256, 3)
void router_main(const float* __restrict__ x,
                 const float* __restrict__ W,
                 const float* __restrict__ gamma,
                 const float* __restrict__ beta,
                 const float* __restrict__ temp,
                 float* __restrict__ out,
                 int N, int Drt, int nTiles)
{
    const int D = DD ? DD : Drt;
    const int Dq = D >> 2;                       // D in float4 units
    const int nIter = D >> 7;                    // 128 floats per warp sweep

    __shared__ float s_logits[TOK_PER_BLOCK * EXPERTS];
    __shared__ bool s_last;

    const int lane = threadIdx.x & 31;
    const int warp = threadIdx.x >> 5;
    const float4* wq = (const float4*)W + lane;

    for (int tile = blockIdx.x; tile < nTiles; tile += GRID_BLOCKS) {
        const int tok0 = tile * TOK_PER_BLOCK + warp * TOK_PER_WARP;
        const int t0 = min(tok0 + 0, N - 1);     // clamp tail (dup, masked)
        const int t1 = min(tok0 + 1, N - 1);
        const float4* xq0 = (const float4*)x + (size_t)t0 * Dq + lane;
        const float4* xq1 = (const float4*)x + (size_t)t1 * Dq + lane;

        u64 acc[TOK_PER_WARP][EXPERTS / 2];
#pragma unroll
        for (int t = 0; t < TOK_PER_WARP; ++t)
#pragma unroll
            for (int j = 0; j < EXPERTS / 2; ++j) acc[t][j] = 0ull;

        // distance-2 software pipeline on x
        float4 c0 = __ldg(xq0);
        float4 c1 = __ldg(xq1);
        const int i1c = min(1, nIter - 1);
        float4 n0 = __ldg(xq0 + (size_t)i1c * 32);
        float4 n1 = __ldg(xq1 + (size_t)i1c * 32);

        for (int i = 0; i < nIter; ++i) {
            const int ip = min(i + 2, nIter - 1);     // branchless prefetch idx
            float4 f0 = __ldg(xq0 + (size_t)ip * 32);
            float4 f1 = __ldg(xq1 + (size_t)ip * 32);

            u64 xx0[4], xx1[4];
#pragma unroll
            for (int d = 0; d < 4; ++d) {
                xx0[d] = pk2(f4c(c0, d), f4c(c0, d));
                xx1[d] = pk2(f4c(c1, d), f4c(c1, d));
            }

#pragma unroll
            for (int h = 0; h < 2; ++h) {             // experts [4h, 4h+4)
                float4 wv[4];
#pragma unroll
                for (int e = 0; e < 4; ++e)
                    wv[e] = __ldg(wq + (size_t)(h * 4 + e) * Dq + (size_t)i * 32);
#pragma unroll
                for (int d = 0; d < 4; ++d) {
                    u64 wp0 = pk2(f4c(wv[0], d), f4c(wv[1], d));
                    u64 wp1 = pk2(f4c(wv[2], d), f4c(wv[3], d));
                    acc[0][h * 2 + 0] = fma2(xx0[d], wp0, acc[0][h * 2 + 0]);
                    acc[0][h * 2 + 1] = fma2(xx0[d], wp1, acc[0][h * 2 + 1]);
                    acc[1][h * 2 + 0] = fma2(xx1[d], wp0, acc[1][h * 2 + 0]);
                    acc[1][h * 2 + 1] = fma2(xx1[d], wp1, acc[1][h * 2 + 1]);
                }
            }
            c0 = n0; c1 = n1; n0 = f0; n1 = f1;
        }

        // butterfly reduce 8 packed accumulators across the warp
#pragma unroll
        for (int m = 16; m >= 1; m >>= 1)
#pragma unroll
            for (int t = 0; t < TOK_PER_WARP; ++t)
#pragma unroll
                for (int j = 0; j < EXPERTS / 2; ++j)
                    acc[t][j] = add2(acc[t][j],
                                     __shfl_xor_sync(0xFFFFFFFFu, acc[t][j], m));

        if (lane == 0) {
#pragma unroll
            for (int t = 0; t < TOK_PER_WARP; ++t)
#pragma unroll
                for (int j = 0; j < EXPERTS / 2; ++j) {
                    float lo, hi;
                    unpk2(acc[t][j], lo, hi);
                    const int lt = warp * TOK_PER_WARP + t;
                    s_logits[lt * EXPERTS + 2 * j + 0] = lo;
                    s_logits[lt * EXPERTS + 2 * j + 1] = hi;
                }
        }
        __syncthreads();

        // ---- epilogue: lanes 0..15 handle this tile's 16 tokens -----------
        if (threadIdx.x < TOK_PER_BLOCK) {
            const int lt = threadIdx.x;
            const int g = tile * TOK_PER_BLOCK + lt;
            const bool valid = (g < N);

            const float tinv = 1.0f / (fabsf(temp[0]) + 1e-6f);
            float gm[EXPERTS], bt[EXPERTS];
#pragma unroll
            for (int e = 0; e < EXPERTS; ++e) { gm[e] = gamma[e]; bt[e] = beta[e]; }

            float l[EXPERTS];
            float mu = 0.0f;
#pragma unroll
            for (int e = 0; e < EXPERTS; ++e) {
                l[e] = s_logits[lt * EXPERTS + e];
                mu += l[e];
            }
            mu *= (1.0f / EXPERTS);
            float var = 0.0f;
#pragma unroll
            for (int e = 0; e < EXPERTS; ++e) {
                float dlt = l[e] - mu;
                var += dlt * dlt;
            }
            var *= (1.0f / EXPERTS);
            const float rinv = rsqrtf(var + 1e-5f);

            float rl[EXPERTS];
            float zsum = 0.0f;
            float mx = -1e30f;
#pragma unroll
            for (int e = 0; e < EXPERTS; ++e) {
                float v = ((l[e] - mu) * rinv * gm[e] + bt[e]) * tinv;
                rl[e] = v;
                zsum += v * v;
                mx = fmaxf(mx, v);
            }
            float rw[EXPERTS];
            float ssum = 0.0f;
#pragma unroll
            for (int e = 0; e < EXPERTS; ++e) {
                rw[e] = expf(rl[e] - mx);
                ssum += rw[e];
            }
            const float sinv = 1.0f / ssum;
#pragma unroll
            for (int e = 0; e < EXPERTS; ++e) rw[e] *= sinv;

            // top-2 (lowest index wins ties, matching lax.top_k)
            int i1 = 0; float w1 = rw[0];
#pragma unroll
            for (int e = 1; e < EXPERTS; ++e)
                if (rw[e] > w1) { w1 = rw[e]; i1 = e; }
            int i2 = -1; float w2 = -1.0f;
#pragma unroll
            for (int e = 0; e < EXPERTS; ++e)
                if (e != i1 && rw[e] > w2) { w2 = rw[e]; i2 = e; }
            const float nrm = 1.0f / (w1 + w2 + 1e-6f);
            const float d1 = w1 * nrm, d2 = w2 * nrm;

            if (valid) {
                const size_t NE = (size_t)N * EXPERTS;
                float4* rwo = (float4*)(out + (size_t)g * EXPERTS);
                rwo[0] = make_float4(rw[0], rw[1], rw[2], rw[3]);
                rwo[1] = make_float4(rw[4], rw[5], rw[6], rw[7]);
                float disp[EXPERTS];
#pragma unroll
                for (int e = 0; e < EXPERTS; ++e)
                    disp[e] = (e == i1) ? d1 : (e == i2) ? d2 : 0.0f;
                float4* dpo = (float4*)(out + NE + (size_t)g * EXPERTS);
                dpo[0] = make_float4(disp[0], disp[1], disp[2], disp[3]);
                dpo[1] = make_float4(disp[4], disp[5], disp[6], disp[7]);
            }

            // 16-lane reduction of tile partials, then single store
            float zc = valid ? zsum : 0.0f;
            float ec[EXPERTS];
#pragma unroll
            for (int e = 0; e < EXPERTS; ++e) ec[e] = valid ? rw[e] : 0.0f;

#pragma unroll
            for (int m = 8; m >= 1; m >>= 1) {
                zc += __shfl_xor_sync(0x0000FFFFu, zc, m);
#pragma unroll
                for (int e = 0; e < EXPERTS; ++e)
                    ec[e] += __shfl_xor_sync(0x0000FFFFu, ec[e], m);
            }
            if (lane == 0) {
                float* p = &g_part[(size_t)tile * 9];
#pragma unroll
                for (int e = 0; e < EXPERTS; ++e) p[e] = ec[e];
                p[8] = zc;
            }
        }
        __syncthreads();

        // ---- per-tile ticket; last tile triggers the loss reduction -------
        if (threadIdx.x == 0) {
            __threadfence();
            unsigned int t = atomicAdd(&g_ctr, 1u);
            s_last = (t == (unsigned int)(nTiles - 1));
        }
        __syncthreads();

        if (s_last) {
            __shared__ float s_red[9];
            for (int c = warp; c < 9; c += WARPS_PER_BLOCK) {
                float v = 0.0f;
                for (int k = lane; k < nTiles; k += 32)
                    v += g_part[(size_t)k * 9 + c];
#pragma unroll
                for (int m = 16; m >= 1; m >>= 1)
                    v += __shfl_xor_sync(0xFFFFFFFFu, v, m);
                if (lane == 0) s_red[c] = v;
            }
            __syncthreads();
            if (threadIdx.x == 0) {
                const float invN = 1.0f / (float)N;
                float z = s_red[8] * invN * (1.0f / EXPERTS);
                float lb = 0.0f;
                const float ideal = 1.0f / EXPERTS;
#pragma unroll
                for (int e = 0; e < EXPERTS; ++e) {
                    float actual = s_red[e] * invN;
                    lb += ideal * (logf(ideal) - logf(actual));
                }
                lb *= (1.0f / EXPERTS);
                out[(size_t)2 * N * EXPERTS] = 0.01f * z + 0.01f * lb;
                g_ctr = 0;   // reset for next graph replay (deterministic)
            }
            __syncthreads();
        }
    }
}

extern "C" void kernel_launch(void* const* d_in, const int* in_sizes, int n_in,
                              void* d_out, int out_size)
{
    const float* x     = (const float*)d_in[0];
    const float* W     = (const float*)d_in[1];
    const float* gamma = (const float*)d_in[2];
    const float* beta  = (const float*)d_in[3];
    const float* temp  = (const float*)d_in[4];
    float* out = (float*)d_out;

    const int E = in_sizes[2];           // 8
    const int D = in_sizes[1] / E;       // 2048
    const int N = in_sizes[0] / D;       // 16384

    const int nTiles = (N + TOK_PER_BLOCK - 1) / TOK_PER_BLOCK;
    const int grid = nTiles < GRID_BLOCKS ? nTiles : GRID_BLOCKS;

    if (D == 2048)
        router_main<2048><<<grid, 256>>>(x, W, gamma, beta, temp, out, N, D, nTiles);
    else
        router_main<0><<<grid, 256>>>(x, W, gamma, beta, temp, out, N, D, nTiles);
}